// round 1
// baseline (speedup 1.0000x reference)
#include <cuda_runtime.h>
#include <math.h>

// Problem constants
#define NB   4
#define CC   256
#define HH   64
#define WW   64
#define HWSZ 4096        // H*W
#define MTOK 16384       // N*H*W tokens
#define GG   8
#define PP   9
#define CG   32          // C/G
#define NOFF 144         // G*P*2
#define NMSK 72          // G*P

// Scratch (no allocs allowed)
__device__ float g_xn [MTOK * CC];   // NHWC input
__device__ float g_xv [MTOK * CC];   // value proj
__device__ float g_x1 [MTOK * CC];   // conv+LN+GELU
__device__ float g_off[MTOK * NOFF];
__device__ float g_ml [MTOK * NMSK]; // mask logits
__device__ float g_mask[MTOK * NMSK];
__device__ float g_y  [MTOK * CC];   // sampled output

// ---------------------------------------------------------------------------
// 1) NCHW -> NHWC transpose (per n: [C][HW] -> [HW][C]), 32x32 smem tiles
// ---------------------------------------------------------------------------
__global__ void transpose_kernel(const float* __restrict__ in) {
    __shared__ float tile[32][33];
    int n   = blockIdx.z;
    int hw0 = blockIdx.x * 32;
    int c0  = blockIdx.y * 32;
    #pragma unroll
    for (int j = 0; j < 4; j++) {
        int cr = threadIdx.y + 8 * j;
        tile[cr][threadIdx.x] =
            in[((size_t)n * CC + (c0 + cr)) * HWSZ + hw0 + threadIdx.x];
    }
    __syncthreads();
    #pragma unroll
    for (int j = 0; j < 4; j++) {
        int r = threadIdx.y + 8 * j;
        g_xn[((size_t)n * HWSZ + hw0 + r) * CC + c0 + threadIdx.x] =
            tile[threadIdx.x][r];
    }
}

// ---------------------------------------------------------------------------
// Tiled fp32 GEMM: C[M,Nn] = A[M,K] @ B[K,Nn] + bias. BM=BN=64, BK=16,
// 256 threads, 4x4 per thread. M % 64 == 0, K % 16 == 0; Nn guarded.
// ---------------------------------------------------------------------------
#define BM 64
#define BN 64
#define BK 16

__device__ __forceinline__ void gemm_core(
    const float* __restrict__ A, const float* __restrict__ B,
    int Nn, int K, int m0, int n0, float acc[4][4],
    float (*As)[BM], float (*Bs)[BN])
{
    int tid = threadIdx.x;
    int tx = tid & 15, ty = tid >> 4;
    for (int k0 = 0; k0 < K; k0 += BK) {
        // A tile: 64 rows x 16 k, one float4 per thread along K
        {
            int r  = tid >> 2;
            int c4 = (tid & 3) * 4;
            float4 v = *(const float4*)&A[(size_t)(m0 + r) * K + k0 + c4];
            As[c4 + 0][r] = v.x; As[c4 + 1][r] = v.y;
            As[c4 + 2][r] = v.z; As[c4 + 3][r] = v.w;
        }
        // B tile: 16 k x 64 n, one float4 per thread along N (guarded)
        {
            int r = tid >> 4;
            int c = (tid & 15) * 4;
            int gn = n0 + c;
            float4 v;
            if (gn + 3 < Nn) {
                v = *(const float4*)&B[(size_t)(k0 + r) * Nn + gn];
            } else {
                v.x = (gn + 0 < Nn) ? B[(size_t)(k0 + r) * Nn + gn + 0] : 0.f;
                v.y = (gn + 1 < Nn) ? B[(size_t)(k0 + r) * Nn + gn + 1] : 0.f;
                v.z = (gn + 2 < Nn) ? B[(size_t)(k0 + r) * Nn + gn + 2] : 0.f;
                v.w = (gn + 3 < Nn) ? B[(size_t)(k0 + r) * Nn + gn + 3] : 0.f;
            }
            Bs[r][c + 0] = v.x; Bs[r][c + 1] = v.y;
            Bs[r][c + 2] = v.z; Bs[r][c + 3] = v.w;
        }
        __syncthreads();
        #pragma unroll
        for (int kk = 0; kk < BK; kk++) {
            float4 a = *(const float4*)&As[kk][ty * 4];
            float4 b = *(const float4*)&Bs[kk][tx * 4];
            float av[4] = {a.x, a.y, a.z, a.w};
            float bv[4] = {b.x, b.y, b.z, b.w};
            #pragma unroll
            for (int i = 0; i < 4; i++)
                #pragma unroll
                for (int j = 0; j < 4; j++)
                    acc[i][j] = fmaf(av[i], bv[j], acc[i][j]);
        }
        __syncthreads();
    }
}

__global__ void gemm_kernel(const float* __restrict__ A,
                            const float* __restrict__ B,
                            const float* __restrict__ bias,
                            float* __restrict__ Cout,
                            int Nn, int K) {
    __shared__ float As[BK][BM];
    __shared__ float Bs[BK][BN];
    int m0 = blockIdx.y * BM;
    int n0 = blockIdx.x * BN;
    float acc[4][4] = {};
    gemm_core(A, B, Nn, K, m0, n0, acc, As, Bs);
    int tx = threadIdx.x & 15, ty = threadIdx.x >> 4;
    #pragma unroll
    for (int i = 0; i < 4; i++)
        #pragma unroll
        for (int j = 0; j < 4; j++) {
            int gn = n0 + tx * 4 + j;
            if (gn < Nn)
                Cout[(size_t)(m0 + ty * 4 + i) * Nn + gn] = acc[i][j] + bias[gn];
        }
}

// Output-proj GEMM with NCHW store: out[n][co][hw] = y[t] @ w_out + b_out
__global__ void gemm_nchw_kernel(const float* __restrict__ A,
                                 const float* __restrict__ B,
                                 const float* __restrict__ bias,
                                 float* __restrict__ Cout,
                                 int Nn, int K) {
    __shared__ float As[BK][BM];
    __shared__ float Bs[BK][BN];
    int m0 = blockIdx.y * BM;
    int n0 = blockIdx.x * BN;
    float acc[4][4] = {};
    gemm_core(A, B, Nn, K, m0, n0, acc, As, Bs);
    int tx = threadIdx.x & 15, ty = threadIdx.x >> 4;
    #pragma unroll
    for (int i = 0; i < 4; i++) {
        int t = m0 + ty * 4 + i;
        int n = t >> 12, hw = t & 4095;
        #pragma unroll
        for (int j = 0; j < 4; j++) {
            int gn = n0 + tx * 4 + j;
            Cout[((size_t)n * CC + gn) * HWSZ + hw] = acc[i][j] + bias[gn];
        }
    }
}

// ---------------------------------------------------------------------------
// 3) depthwise 3x3 conv + LayerNorm + exact GELU. One block = one token.
// ---------------------------------------------------------------------------
__global__ void conv_ln_gelu_kernel(const float* __restrict__ dwk,
                                    const float* __restrict__ dwb,
                                    const float* __restrict__ lng,
                                    const float* __restrict__ lnb) {
    int t = blockIdx.x;
    int c = threadIdx.x;
    int n = t >> 12, hw = t & 4095, h = hw >> 6, w = hw & 63;

    float acc = dwb[c];
    #pragma unroll
    for (int kh = 0; kh < 3; kh++) {
        int hh = h + kh - 1;
        if (hh < 0 || hh >= HH) continue;
        #pragma unroll
        for (int kw = 0; kw < 3; kw++) {
            int ww = w + kw - 1;
            if (ww < 0 || ww >= WW) continue;
            acc = fmaf(g_xn[((size_t)n * HWSZ + hh * WW + ww) * CC + c],
                       dwk[(kh * 3 + kw) * CC + c], acc);
        }
    }

    __shared__ float s1[256], s2[256];
    s1[c] = acc;
    s2[c] = acc * acc;
    __syncthreads();
    for (int s = 128; s > 0; s >>= 1) {
        if (c < s) { s1[c] += s1[c + s]; s2[c] += s2[c + s]; }
        __syncthreads();
    }
    float mu  = s1[0] * (1.0f / 256.0f);
    float var = s2[0] * (1.0f / 256.0f) - mu * mu;
    float v = (acc - mu) * rsqrtf(var + 1e-6f) * lng[c] + lnb[c];
    // exact GELU
    v = 0.5f * v * (1.0f + erff(v * 0.70710678118654752f));
    g_x1[(size_t)t * CC + c] = v;
}

// ---------------------------------------------------------------------------
// 5) softmax over P per (token, group)
// ---------------------------------------------------------------------------
__global__ void softmax_kernel() {
    int i = blockIdx.x * blockDim.x + threadIdx.x;   // t*G + g
    if (i >= MTOK * GG) return;
    const float* src = g_ml + (size_t)i * PP;
    float mx = src[0];
    #pragma unroll
    for (int p = 1; p < PP; p++) mx = fmaxf(mx, src[p]);
    float e[PP], s = 0.f;
    #pragma unroll
    for (int p = 0; p < PP; p++) { e[p] = __expf(src[p] - mx); s += e[p]; }
    float inv = 1.0f / s;
    #pragma unroll
    for (int p = 0; p < PP; p++) g_mask[(size_t)i * PP + p] = e[p] * inv;
}

// ---------------------------------------------------------------------------
// 6) DCNv3 bilinear sampling. One warp = one (token, group), lane = channel.
// ---------------------------------------------------------------------------
__global__ void dcn_kernel() {
    int t = blockIdx.x;
    int g = threadIdx.x >> 5;
    int lane = threadIdx.x & 31;
    int n = t >> 12, hw = t & 4095, h = hw >> 6, w = hw & 63;

    const float* off = g_off  + (size_t)t * NOFF + g * (PP * 2);
    const float* mk  = g_mask + (size_t)t * NMSK + g * PP;
    const float* xvb = g_xv + (size_t)n * HWSZ * CC + g * CG + lane;

    float acc = 0.f;
    #pragma unroll
    for (int p = 0; p < PP; p++) {
        float kx = (float)(p / 3 - 1);
        float ky = (float)(p % 3 - 1);
        float px = (float)w + 1.0f + 2.0f * (kx + off[p * 2 + 0]);
        float py = (float)h + 1.0f + 2.0f * (ky + off[p * 2 + 1]);
        float x0f = floorf(px), y0f = floorf(py);
        float wx = px - x0f, wy = py - y0f;
        int x0 = (int)x0f, y0 = (int)y0f;
        float m = mk[p];

        float v00 = 0.f, v01 = 0.f, v10 = 0.f, v11 = 0.f;
        // padded map is Hp=Wp=66 with zero ring; value nonzero only for
        // xi in [1,64], yi in [1,64] -> xv[(yi-1)*64 + (xi-1)]
        if (x0 >= 1 && x0 <= WW && y0 >= 1 && y0 <= HH)
            v00 = xvb[((size_t)(y0 - 1) * WW + (x0 - 1)) * CC];
        if (x0 + 1 >= 1 && x0 + 1 <= WW && y0 >= 1 && y0 <= HH)
            v01 = xvb[((size_t)(y0 - 1) * WW + x0) * CC];
        if (x0 >= 1 && x0 <= WW && y0 + 1 >= 1 && y0 + 1 <= HH)
            v10 = xvb[((size_t)y0 * WW + (x0 - 1)) * CC];
        if (x0 + 1 >= 1 && x0 + 1 <= WW && y0 + 1 >= 1 && y0 + 1 <= HH)
            v11 = xvb[((size_t)y0 * WW + x0) * CC];

        float top = v00 * (1.f - wx) + v01 * wx;
        float bot = v10 * (1.f - wx) + v11 * wx;
        acc = fmaf(m, top * (1.f - wy) + bot * wy, acc);
    }
    g_y[(size_t)t * CC + g * CG + lane] = acc;
}

// ---------------------------------------------------------------------------
extern "C" void kernel_launch(void* const* d_in, const int* in_sizes, int n_in,
                              void* d_out, int out_size) {
    const float* inputs = (const float*)d_in[0];
    const float* w_in   = (const float*)d_in[1];
    const float* b_in   = (const float*)d_in[2];
    const float* dw_k   = (const float*)d_in[3];
    const float* dw_b   = (const float*)d_in[4];
    const float* ln_g   = (const float*)d_in[5];
    const float* ln_b   = (const float*)d_in[6];
    const float* w_off  = (const float*)d_in[7];
    const float* b_off  = (const float*)d_in[8];
    const float* w_mask = (const float*)d_in[9];
    const float* b_mask = (const float*)d_in[10];
    const float* w_out  = (const float*)d_in[11];
    const float* b_out  = (const float*)d_in[12];
    float* out = (float*)d_out;

    static float *p_xn = nullptr, *p_xv = nullptr, *p_x1 = nullptr,
                 *p_off = nullptr, *p_ml = nullptr, *p_y = nullptr;
    if (!p_xn) {
        cudaGetSymbolAddress((void**)&p_xn,  g_xn);
        cudaGetSymbolAddress((void**)&p_xv,  g_xv);
        cudaGetSymbolAddress((void**)&p_x1,  g_x1);
        cudaGetSymbolAddress((void**)&p_off, g_off);
        cudaGetSymbolAddress((void**)&p_ml,  g_ml);
        cudaGetSymbolAddress((void**)&p_y,   g_y);
    }

    // 1) NCHW -> NHWC
    transpose_kernel<<<dim3(HWSZ / 32, CC / 32, NB), dim3(32, 8)>>>(inputs);
    // 2) value projection
    gemm_kernel<<<dim3(CC / BN, MTOK / BM), 256>>>(p_xn, w_in, b_in, p_xv, CC, CC);
    // 3) depthwise conv + LN + GELU
    conv_ln_gelu_kernel<<<MTOK, 256>>>(dw_k, dw_b, ln_g, ln_b);
    // 4) offset + mask logits
    gemm_kernel<<<dim3((NOFF + BN - 1) / BN, MTOK / BM), 256>>>(p_x1, w_off, b_off, p_off, NOFF, CC);
    gemm_kernel<<<dim3((NMSK + BN - 1) / BN, MTOK / BM), 256>>>(p_x1, w_mask, b_mask, p_ml, NMSK, CC);
    // 5) softmax over P
    softmax_kernel<<<(MTOK * GG + 255) / 256, 256>>>();
    // 6) deformable sampling
    dcn_kernel<<<MTOK, 256>>>();
    // 7) output projection, NCHW store
    gemm_nchw_kernel<<<dim3(CC / BN, MTOK / BM), 256>>>(p_y, w_out, b_out, out, CC, CC);
}

// round 2
// speedup vs baseline: 1.1209x; 1.1209x over previous
#include <cuda_runtime.h>
#include <math.h>
#include <stdint.h>

// Problem constants
#define NB   4
#define CC   256
#define HH   64
#define WW   64
#define HWSZ 4096        // H*W
#define MTOK 16384       // N*H*W tokens
#define GG   8
#define PP   9
#define CG   32          // C/G
#define NOFF 144         // G*P*2
#define NMSK 72          // G*P
#define NCAT 256         // padded off|mask column count

// Scratch (no allocs allowed)
__device__ float g_xn  [MTOK * CC];    // NHWC input
__device__ float g_xv  [MTOK * CC];    // value proj
__device__ float g_x1  [MTOK * CC];    // conv+LN+GELU
__device__ float g_om  [MTOK * NCAT];  // offset(0..143) | mask logits(144..215) | pad
__device__ float g_y   [MTOK * CC];    // sampled output
__device__ float g_win [CC * CC];      // tf32-rounded w_in
__device__ float g_wout[CC * CC];      // tf32-rounded w_out
__device__ float g_wcat[CC * NCAT];    // tf32-rounded [w_off | w_mask | 0]
__device__ float g_bcat[NCAT];

__device__ __forceinline__ float tf32r(float x) {
    uint32_t u;
    asm("cvt.rna.tf32.f32 %0, %1;" : "=r"(u) : "f"(x));
    return __uint_as_float(u);
}

__device__ __forceinline__ void mma_tf32(float d[4], const uint32_t a[4], const uint32_t b[2]) {
    asm("mma.sync.aligned.m16n8k8.row.col.f32.tf32.tf32.f32 "
        "{%0,%1,%2,%3}, {%4,%5,%6,%7}, {%8,%9}, {%0,%1,%2,%3};"
        : "+f"(d[0]), "+f"(d[1]), "+f"(d[2]), "+f"(d[3])
        : "r"(a[0]), "r"(a[1]), "r"(a[2]), "r"(a[3]), "r"(b[0]), "r"(b[1]));
}

// ---------------------------------------------------------------------------
// 0) Pack + tf32-round weights
// ---------------------------------------------------------------------------
__global__ void pack_kernel(const float* __restrict__ w_in,
                            const float* __restrict__ w_off,
                            const float* __restrict__ b_off,
                            const float* __restrict__ w_mask,
                            const float* __restrict__ b_mask,
                            const float* __restrict__ w_out) {
    int k = blockIdx.x;    // 0..255 (input channel)
    int n = threadIdx.x;   // 0..255 (output col)
    g_win [k * CC + n] = tf32r(w_in [k * CC + n]);
    g_wout[k * CC + n] = tf32r(w_out[k * CC + n]);
    float v = (n < NOFF) ? w_off[k * NOFF + n]
            : (n < NOFF + NMSK) ? w_mask[k * NMSK + (n - NOFF)] : 0.f;
    g_wcat[k * NCAT + n] = tf32r(v);
    if (k == 0)
        g_bcat[n] = (n < NOFF) ? b_off[n]
                  : (n < NOFF + NMSK) ? b_mask[n - NOFF] : 0.f;
}

// ---------------------------------------------------------------------------
// 1) NCHW -> NHWC transpose
// ---------------------------------------------------------------------------
__global__ void transpose_kernel(const float* __restrict__ in) {
    __shared__ float tile[32][33];
    int n   = blockIdx.z;
    int hw0 = blockIdx.x * 32;
    int c0  = blockIdx.y * 32;
    #pragma unroll
    for (int j = 0; j < 4; j++) {
        int cr = threadIdx.y + 8 * j;
        tile[cr][threadIdx.x] =
            in[((size_t)n * CC + (c0 + cr)) * HWSZ + hw0 + threadIdx.x];
    }
    __syncthreads();
    #pragma unroll
    for (int j = 0; j < 4; j++) {
        int r = threadIdx.y + 8 * j;
        g_xn[((size_t)n * HWSZ + hw0 + r) * CC + c0 + threadIdx.x] =
            tile[threadIdx.x][r];
    }
}

// ---------------------------------------------------------------------------
// TF32 tensor-core GEMM: C[M,256] = A[M,256] @ B[256,256] + bias
// CTA 128x128x16, 8 warps (4 m x 2 n), warp tile 32x64, double-buffered smem.
// A is fp32 (converted to tf32 on smem staging); B is pre-rounded tf32.
// STORE_NCHW: 0 -> row-major [M,256]; 1 -> NCHW [4][256][4096]
// ---------------------------------------------------------------------------
#define GBM 128
#define GBN 128
#define GBK 16
#define SPAD 136   // padded row stride (floats): keeps 16B align, spreads banks
#define KTOT 256
#define NKT (KTOT / GBK)

template<int STORE_NCHW>
__global__ void __launch_bounds__(256, 2)
gemm_tf32(const float* __restrict__ A, const float* __restrict__ B,
          const float* __restrict__ bias, float* __restrict__ Cout) {
    __shared__ float As[2][GBK][SPAD];
    __shared__ float Bs[2][GBK][SPAD];

    int tid  = threadIdx.x;
    int lane = tid & 31;
    int warp = tid >> 5;
    int gid  = lane >> 2;     // 0..7
    int tid4 = lane & 3;      // 0..3
    int wm   = warp >> 1;     // 0..3
    int wn   = warp & 1;      // 0..1
    int m0   = blockIdx.y * GBM;
    int n0   = blockIdx.x * GBN;

    // staging indices
    int ar = tid >> 1;             // A row within tile (0..127)
    int ac = (tid & 1) * 8;        // A k offset (0 or 8)
    int br = tid >> 4;             // B k row (0..15)
    int bc = (tid & 15) * 8;       // B n col

    const float* Aptr = A + (size_t)(m0 + ar) * KTOT + ac;
    const float* Bptr = B + (size_t)br * NCAT + n0 + bc;

    float acc[2][8][4];
    #pragma unroll
    for (int i = 0; i < 2; i++)
        #pragma unroll
        for (int j = 0; j < 8; j++)
            #pragma unroll
            for (int q = 0; q < 4; q++) acc[i][j][q] = 0.f;

    float4 pa0, pa1, pb0, pb1;

    // prologue: load k-tile 0
    pa0 = *(const float4*)(Aptr + 0);
    pa1 = *(const float4*)(Aptr + 4);
    pb0 = *(const float4*)(Bptr + 0);
    pb1 = *(const float4*)(Bptr + 4);
    {
        As[0][ac + 0][ar] = tf32r(pa0.x); As[0][ac + 1][ar] = tf32r(pa0.y);
        As[0][ac + 2][ar] = tf32r(pa0.z); As[0][ac + 3][ar] = tf32r(pa0.w);
        As[0][ac + 4][ar] = tf32r(pa1.x); As[0][ac + 5][ar] = tf32r(pa1.y);
        As[0][ac + 6][ar] = tf32r(pa1.z); As[0][ac + 7][ar] = tf32r(pa1.w);
        *(float4*)&Bs[0][br][bc]     = pb0;
        *(float4*)&Bs[0][br][bc + 4] = pb1;
    }
    __syncthreads();

    for (int kt = 0; kt < NKT; kt++) {
        int cur = kt & 1;
        if (kt + 1 < NKT) {
            const float* An = Aptr + (kt + 1) * GBK;
            const float* Bn = Bptr + (size_t)(kt + 1) * GBK * NCAT;
            pa0 = *(const float4*)(An + 0);
            pa1 = *(const float4*)(An + 4);
            pb0 = *(const float4*)(Bn + 0);
            pb1 = *(const float4*)(Bn + 4);
        }
        // compute current tile
        #pragma unroll
        for (int ks = 0; ks < 2; ks++) {
            int kk = ks * 8;
            uint32_t af[2][4], bf[8][2];
            #pragma unroll
            for (int mt = 0; mt < 2; mt++) {
                int mb = wm * 32 + mt * 16;
                af[mt][0] = __float_as_uint(As[cur][kk + tid4    ][mb + gid    ]);
                af[mt][1] = __float_as_uint(As[cur][kk + tid4    ][mb + gid + 8]);
                af[mt][2] = __float_as_uint(As[cur][kk + tid4 + 4][mb + gid    ]);
                af[mt][3] = __float_as_uint(As[cur][kk + tid4 + 4][mb + gid + 8]);
            }
            #pragma unroll
            for (int nt = 0; nt < 8; nt++) {
                int nb = wn * 64 + nt * 8;
                bf[nt][0] = __float_as_uint(Bs[cur][kk + tid4    ][nb + gid]);
                bf[nt][1] = __float_as_uint(Bs[cur][kk + tid4 + 4][nb + gid]);
            }
            #pragma unroll
            for (int mt = 0; mt < 2; mt++)
                #pragma unroll
                for (int nt = 0; nt < 8; nt++)
                    mma_tf32(acc[mt][nt], af[mt], bf[nt]);
        }
        if (kt + 1 < NKT) {
            int nxt = cur ^ 1;
            As[nxt][ac + 0][ar] = tf32r(pa0.x); As[nxt][ac + 1][ar] = tf32r(pa0.y);
            As[nxt][ac + 2][ar] = tf32r(pa0.z); As[nxt][ac + 3][ar] = tf32r(pa0.w);
            As[nxt][ac + 4][ar] = tf32r(pa1.x); As[nxt][ac + 5][ar] = tf32r(pa1.y);
            As[nxt][ac + 6][ar] = tf32r(pa1.z); As[nxt][ac + 7][ar] = tf32r(pa1.w);
            *(float4*)&Bs[nxt][br][bc]     = pb0;
            *(float4*)&Bs[nxt][br][bc + 4] = pb1;
            __syncthreads();
        }
    }

    // epilogue
    #pragma unroll
    for (int mt = 0; mt < 2; mt++) {
        int r0 = m0 + wm * 32 + mt * 16 + gid;
        #pragma unroll
        for (int nt = 0; nt < 8; nt++) {
            int cb = n0 + wn * 64 + nt * 8 + 2 * tid4;
            float b0 = bias[cb], b1 = bias[cb + 1];
            if (STORE_NCHW) {
                int n0b = r0 >> 12, hw0 = r0 & 4095;
                int n1b = (r0 + 8) >> 12, hw1 = (r0 + 8) & 4095;
                Cout[((size_t)n0b * CC + cb    ) * HWSZ + hw0] = acc[mt][nt][0] + b0;
                Cout[((size_t)n0b * CC + cb + 1) * HWSZ + hw0] = acc[mt][nt][1] + b1;
                Cout[((size_t)n1b * CC + cb    ) * HWSZ + hw1] = acc[mt][nt][2] + b0;
                Cout[((size_t)n1b * CC + cb + 1) * HWSZ + hw1] = acc[mt][nt][3] + b1;
            } else {
                Cout[(size_t)r0 * NCAT + cb]           = acc[mt][nt][0] + b0;
                Cout[(size_t)r0 * NCAT + cb + 1]       = acc[mt][nt][1] + b1;
                Cout[(size_t)(r0 + 8) * NCAT + cb]     = acc[mt][nt][2] + b0;
                Cout[(size_t)(r0 + 8) * NCAT + cb + 1] = acc[mt][nt][3] + b1;
            }
        }
    }
}

// ---------------------------------------------------------------------------
// 3) depthwise 3x3 conv + LayerNorm + exact GELU. One block = one token.
// ---------------------------------------------------------------------------
__global__ void conv_ln_gelu_kernel(const float* __restrict__ dwk,
                                    const float* __restrict__ dwb,
                                    const float* __restrict__ lng,
                                    const float* __restrict__ lnb) {
    int t = blockIdx.x;
    int c = threadIdx.x;
    int n = t >> 12, hw = t & 4095, h = hw >> 6, w = hw & 63;

    float acc = dwb[c];
    #pragma unroll
    for (int kh = 0; kh < 3; kh++) {
        int hh = h + kh - 1;
        if (hh < 0 || hh >= HH) continue;
        #pragma unroll
        for (int kw = 0; kw < 3; kw++) {
            int ww = w + kw - 1;
            if (ww < 0 || ww >= WW) continue;
            acc = fmaf(g_xn[((size_t)n * HWSZ + hh * WW + ww) * CC + c],
                       dwk[(kh * 3 + kw) * CC + c], acc);
        }
    }

    __shared__ float s1[256], s2[256];
    s1[c] = acc;
    s2[c] = acc * acc;
    __syncthreads();
    for (int s = 128; s > 0; s >>= 1) {
        if (c < s) { s1[c] += s1[c + s]; s2[c] += s2[c + s]; }
        __syncthreads();
    }
    float mu  = s1[0] * (1.0f / 256.0f);
    float var = s2[0] * (1.0f / 256.0f) - mu * mu;
    float v = (acc - mu) * rsqrtf(var + 1e-6f) * lng[c] + lnb[c];
    v = 0.5f * v * (1.0f + erff(v * 0.70710678118654752f));
    g_x1[(size_t)t * CC + c] = v;
}

// ---------------------------------------------------------------------------
// 6) DCNv3 bilinear sampling with fused per-(t,g) softmax over P.
//    One warp = one (token, group), lane = channel.
// ---------------------------------------------------------------------------
__global__ void dcn_kernel() {
    int t = blockIdx.x;
    int g = threadIdx.x >> 5;
    int lane = threadIdx.x & 31;
    int n = t >> 12, hw = t & 4095, h = hw >> 6, w = hw & 63;

    const float* off = g_om + (size_t)t * NCAT + g * (PP * 2);
    const float* lg  = g_om + (size_t)t * NCAT + NOFF + g * PP;
    const float* xvb = g_xv + (size_t)n * HWSZ * CC + g * CG + lane;

    // per-lane softmax over 9 logits (broadcast loads, L1)
    float e[PP];
    float mx = lg[0];
    #pragma unroll
    for (int p = 1; p < PP; p++) mx = fmaxf(mx, lg[p]);
    float s = 0.f;
    #pragma unroll
    for (int p = 0; p < PP; p++) { e[p] = __expf(lg[p] - mx); s += e[p]; }
    float inv = 1.0f / s;

    float acc = 0.f;
    #pragma unroll
    for (int p = 0; p < PP; p++) {
        float kx = (float)(p / 3 - 1);
        float ky = (float)(p % 3 - 1);
        float px = (float)w + 1.0f + 2.0f * (kx + off[p * 2 + 0]);
        float py = (float)h + 1.0f + 2.0f * (ky + off[p * 2 + 1]);
        float x0f = floorf(px), y0f = floorf(py);
        float wx = px - x0f, wy = py - y0f;
        int x0 = (int)x0f, y0 = (int)y0f;
        float m = e[p] * inv;

        float v00 = 0.f, v01 = 0.f, v10 = 0.f, v11 = 0.f;
        if (x0 >= 1 && x0 <= WW && y0 >= 1 && y0 <= HH)
            v00 = xvb[((size_t)(y0 - 1) * WW + (x0 - 1)) * CC];
        if (x0 + 1 >= 1 && x0 + 1 <= WW && y0 >= 1 && y0 <= HH)
            v01 = xvb[((size_t)(y0 - 1) * WW + x0) * CC];
        if (x0 >= 1 && x0 <= WW && y0 + 1 >= 1 && y0 + 1 <= HH)
            v10 = xvb[((size_t)y0 * WW + (x0 - 1)) * CC];
        if (x0 + 1 >= 1 && x0 + 1 <= WW && y0 + 1 >= 1 && y0 + 1 <= HH)
            v11 = xvb[((size_t)y0 * WW + x0) * CC];

        float top = v00 * (1.f - wx) + v01 * wx;
        float bot = v10 * (1.f - wx) + v11 * wx;
        acc = fmaf(m, top * (1.f - wy) + bot * wy, acc);
    }
    g_y[(size_t)t * CC + g * CG + lane] = acc;
}

// ---------------------------------------------------------------------------
extern "C" void kernel_launch(void* const* d_in, const int* in_sizes, int n_in,
                              void* d_out, int out_size) {
    const float* inputs = (const float*)d_in[0];
    const float* w_in   = (const float*)d_in[1];
    const float* b_in   = (const float*)d_in[2];
    const float* dw_k   = (const float*)d_in[3];
    const float* dw_b   = (const float*)d_in[4];
    const float* ln_g   = (const float*)d_in[5];
    const float* ln_b   = (const float*)d_in[6];
    const float* w_off  = (const float*)d_in[7];
    const float* b_off  = (const float*)d_in[8];
    const float* w_mask = (const float*)d_in[9];
    const float* b_mask = (const float*)d_in[10];
    const float* w_out  = (const float*)d_in[11];
    const float* b_out  = (const float*)d_in[12];
    float* out = (float*)d_out;

    static float *p_xn = nullptr, *p_xv = nullptr, *p_x1 = nullptr,
                 *p_om = nullptr, *p_y = nullptr,
                 *p_win = nullptr, *p_wout = nullptr, *p_wcat = nullptr, *p_bcat = nullptr;
    if (!p_xn) {
        cudaGetSymbolAddress((void**)&p_xn,   g_xn);
        cudaGetSymbolAddress((void**)&p_xv,   g_xv);
        cudaGetSymbolAddress((void**)&p_x1,   g_x1);
        cudaGetSymbolAddress((void**)&p_om,   g_om);
        cudaGetSymbolAddress((void**)&p_y,    g_y);
        cudaGetSymbolAddress((void**)&p_win,  g_win);
        cudaGetSymbolAddress((void**)&p_wout, g_wout);
        cudaGetSymbolAddress((void**)&p_wcat, g_wcat);
        cudaGetSymbolAddress((void**)&p_bcat, g_bcat);
    }

    // 0) pack + tf32-round weights
    pack_kernel<<<CC, CC>>>(w_in, w_off, b_off, w_mask, b_mask, w_out);
    // 1) NCHW -> NHWC
    transpose_kernel<<<dim3(HWSZ / 32, CC / 32, NB), dim3(32, 8)>>>(inputs);
    // 2) value projection (tf32 MMA)
    gemm_tf32<0><<<dim3(2, MTOK / GBM), 256>>>(p_xn, p_win, b_in, p_xv);
    // 3) depthwise conv + LN + GELU
    conv_ln_gelu_kernel<<<MTOK, 256>>>(dw_k, dw_b, ln_g, ln_b);
    // 4) offset + mask logits, fused (tf32 MMA)
    gemm_tf32<0><<<dim3(2, MTOK / GBM), 256>>>(p_x1, p_wcat, p_bcat, p_om);
    // 5+6) softmax + deformable sampling
    dcn_kernel<<<MTOK, 256>>>();
    // 7) output projection, NCHW store (tf32 MMA)
    gemm_tf32<1><<<dim3(2, MTOK / GBM), 256>>>(p_y, p_wout, b_out, out);
}

// round 3
// speedup vs baseline: 1.9858x; 1.7715x over previous
#include <cuda_runtime.h>
#include <math.h>
#include <stdint.h>

// Problem constants
#define NB   4
#define CC   256
#define HH   64
#define WW   64
#define HWSZ 4096        // H*W
#define MTOK 16384       // N*H*W tokens
#define GG   8
#define PP   9
#define CG   32          // C/G
#define NOFF 144         // G*P*2
#define NMSK 72          // G*P
#define NCAT 256         // padded off|mask column count

// Scratch (no allocs allowed)
__device__ float g_c1  [MTOK * CC];    // depthwise conv output, NCHW
__device__ float g_xv  [MTOK * CC];    // value proj, NHWC
__device__ float g_x1  [MTOK * CC];    // conv+LN+GELU, NHWC
__device__ float g_om  [MTOK * NCAT];  // offset(0..143) | mask logits(144..215) | pad
__device__ float g_y   [MTOK * CC];    // sampled output, NHWC
__device__ float g_win [CC * CC];      // tf32-rounded w_in
__device__ float g_wout[CC * CC];      // tf32-rounded w_out
__device__ float g_wcat[CC * NCAT];    // tf32-rounded [w_off | w_mask | 0]
__device__ float g_bcat[NCAT];

__device__ __forceinline__ float tf32r(float x) {
    uint32_t u;
    asm("cvt.rna.tf32.f32 %0, %1;" : "=r"(u) : "f"(x));
    return __uint_as_float(u);
}

__device__ __forceinline__ void mma_tf32(float d[4], const uint32_t a[4], const uint32_t b[2]) {
    asm("mma.sync.aligned.m16n8k8.row.col.f32.tf32.tf32.f32 "
        "{%0,%1,%2,%3}, {%4,%5,%6,%7}, {%8,%9}, {%0,%1,%2,%3};"
        : "+f"(d[0]), "+f"(d[1]), "+f"(d[2]), "+f"(d[3])
        : "r"(a[0]), "r"(a[1]), "r"(a[2]), "r"(a[3]), "r"(b[0]), "r"(b[1]));
}

// ---------------------------------------------------------------------------
// 0) Pack + tf32-round weights
// ---------------------------------------------------------------------------
__global__ void pack_kernel(const float* __restrict__ w_in,
                            const float* __restrict__ w_off,
                            const float* __restrict__ b_off,
                            const float* __restrict__ w_mask,
                            const float* __restrict__ b_mask,
                            const float* __restrict__ w_out) {
    int k = blockIdx.x;    // 0..255 (input channel)
    int n = threadIdx.x;   // 0..255 (output col)
    g_win [k * CC + n] = tf32r(w_in [k * CC + n]);
    g_wout[k * CC + n] = tf32r(w_out[k * CC + n]);
    float v = (n < NOFF) ? w_off[k * NOFF + n]
            : (n < NOFF + NMSK) ? w_mask[k * NMSK + (n - NOFF)] : 0.f;
    g_wcat[k * NCAT + n] = tf32r(v);
    if (k == 0)
        g_bcat[n] = (n < NOFF) ? b_off[n]
                  : (n < NOFF + NMSK) ? b_mask[n - NOFF] : 0.f;
}

// ---------------------------------------------------------------------------
// 1) Depthwise 3x3 conv in native NCHW. One block = one (n,c) 64x64 plane.
//    Reads the RAW input (no transpose needed); writes g_c1 in NCHW.
// ---------------------------------------------------------------------------
__global__ void __launch_bounds__(256)
conv_dw_kernel(const float* __restrict__ in,
               const float* __restrict__ dwk,
               const float* __restrict__ dwb) {
    __shared__ float sp[66][66];
    int b = blockIdx.x;
    int n = b >> 8, c = b & 255;
    int tid = threadIdx.x;

    // zero fill (halo ring)
    for (int i = tid; i < 66 * 66; i += 256) ((float*)sp)[i] = 0.f;
    __syncthreads();

    const float* src = in + ((size_t)n * CC + c) * HWSZ;
    for (int i = tid; i < HWSZ; i += 256) {
        int h = i >> 6, w = i & 63;
        sp[h + 1][w + 1] = src[i];
    }
    __syncthreads();

    float k00 = dwk[0 * CC + c], k01 = dwk[1 * CC + c], k02 = dwk[2 * CC + c];
    float k10 = dwk[3 * CC + c], k11 = dwk[4 * CC + c], k12 = dwk[5 * CC + c];
    float k20 = dwk[6 * CC + c], k21 = dwk[7 * CC + c], k22 = dwk[8 * CC + c];
    float bb  = dwb[c];

    float* dst = g_c1 + ((size_t)n * CC + c) * HWSZ;
    for (int i = tid; i < HWSZ; i += 256) {
        int h = i >> 6, w = i & 63;
        float acc = bb;
        acc = fmaf(sp[h    ][w    ], k00, acc);
        acc = fmaf(sp[h    ][w + 1], k01, acc);
        acc = fmaf(sp[h    ][w + 2], k02, acc);
        acc = fmaf(sp[h + 1][w    ], k10, acc);
        acc = fmaf(sp[h + 1][w + 1], k11, acc);
        acc = fmaf(sp[h + 1][w + 2], k12, acc);
        acc = fmaf(sp[h + 2][w    ], k20, acc);
        acc = fmaf(sp[h + 2][w + 1], k21, acc);
        acc = fmaf(sp[h + 2][w + 2], k22, acc);
        dst[i] = acc;
    }
}

// ---------------------------------------------------------------------------
// 2) LayerNorm + exact GELU with NCHW -> NHWC transpose.
//    Block = 32 consecutive tokens x 256 channels, smem tile + shuffle reduce.
// ---------------------------------------------------------------------------
__global__ void __launch_bounds__(256)
ln_gelu_kernel(const float* __restrict__ lng, const float* __restrict__ lnb) {
    __shared__ float tile[256][33];
    __shared__ float smu[32], srs[32];

    int tid = threadIdx.x;
    int t0 = blockIdx.x * 32;
    int n = t0 >> 12, hw0 = t0 & 4095;

    // load: 256 channels x 32 tokens, coalesced along hw
    const float* src = g_c1 + (size_t)n * CC * HWSZ + hw0;
    int tx = tid & 31, ty = tid >> 5;
    #pragma unroll 4
    for (int cc = 0; cc < 32; cc++) {
        int ch = cc * 8 + ty;
        tile[ch][tx] = src[(size_t)ch * HWSZ + tx];
    }
    __syncthreads();

    // reduce: 8 threads per token, each sums 32 channels
    int tok = tid >> 3, thr = tid & 7;
    float s1 = 0.f, s2 = 0.f;
    #pragma unroll 8
    for (int i = 0; i < 32; i++) {
        float v = tile[thr + 8 * i][tok];
        s1 += v; s2 += v * v;
    }
    #pragma unroll
    for (int d = 1; d < 8; d <<= 1) {
        s1 += __shfl_xor_sync(0xffffffffu, s1, d);
        s2 += __shfl_xor_sync(0xffffffffu, s2, d);
    }
    if (thr == 0) {
        float mu = s1 * (1.0f / 256.0f);
        float var = s2 * (1.0f / 256.0f) - mu * mu;
        smu[tok] = mu;
        srs[tok] = rsqrtf(var + 1e-6f);
    }
    __syncthreads();

    // write: thread = channel, iterate tokens; conflict-free (stride 33)
    float gma = lng[tid], bta = lnb[tid];
    #pragma unroll 4
    for (int j = 0; j < 32; j++) {
        float v = (tile[tid][j] - smu[j]) * srs[j] * gma + bta;
        v = 0.5f * v * (1.0f + erff(v * 0.70710678118654752f));
        g_x1[(size_t)(t0 + j) * CC + tid] = v;
    }
}

// ---------------------------------------------------------------------------
// TF32 tensor-core GEMM: C[M,256] = A[M,256] @ B[256,256] + bias
// CTA 128x128x16, 8 warps (4m x 2n), warp tile 32x64, double-buffered smem.
// ATRANS=1: A given as NCHW ([n][K][hw] = per-n column-major A) -> straight copy staging.
// STORE_NCHW=1: store to NCHW [4][256][4096].
// ---------------------------------------------------------------------------
#define GBM 128
#define GBN 128
#define GBK 16
#define SPAD 136
#define KTOT 256
#define NKT (KTOT / GBK)

template<int ATRANS, int STORE_NCHW>
__global__ void __launch_bounds__(256, 2)
gemm_tf32(const float* __restrict__ A, const float* __restrict__ B,
          const float* __restrict__ bias, float* __restrict__ Cout) {
    __shared__ float As[2][GBK][SPAD];
    __shared__ float Bs[2][GBK][SPAD];

    int tid  = threadIdx.x;
    int lane = tid & 31;
    int warp = tid >> 5;
    int gid  = lane >> 2;
    int tid4 = lane & 3;
    int wm   = warp >> 1;
    int wn   = warp & 1;
    int m0   = blockIdx.y * GBM;
    int n0   = blockIdx.x * GBN;

    // staging indices
    int ar = tid >> 1;             // !ATRANS: A row (0..127)
    int ac = (tid & 1) * 8;        // !ATRANS: A k offset
    int br = tid >> 4;             // k row (0..15) for B and ATRANS-A
    int bc = (tid & 15) * 8;       // col offset

    const float* Aptr;
    if (ATRANS) {
        // A^T layout: element (k, m0+mm) at n*CC*HWSZ + k*HWSZ + hw0+mm
        Aptr = A + (size_t)(m0 >> 12) * CC * HWSZ + (size_t)br * HWSZ + (m0 & 4095) + bc;
    } else {
        Aptr = A + (size_t)(m0 + ar) * KTOT + ac;
    }
    const float* Bptr = B + (size_t)br * NCAT + n0 + bc;

    float acc[2][8][4];
    #pragma unroll
    for (int i = 0; i < 2; i++)
        #pragma unroll
        for (int j = 0; j < 8; j++)
            #pragma unroll
            for (int q = 0; q < 4; q++) acc[i][j][q] = 0.f;

    float4 pa0, pa1, pb0, pb1;

    // prologue: k-tile 0
    pa0 = *(const float4*)(Aptr + 0);
    pa1 = *(const float4*)(Aptr + 4);
    pb0 = *(const float4*)(Bptr + 0);
    pb1 = *(const float4*)(Bptr + 4);
    if (ATRANS) {
        float4 c0 = make_float4(tf32r(pa0.x), tf32r(pa0.y), tf32r(pa0.z), tf32r(pa0.w));
        float4 c1 = make_float4(tf32r(pa1.x), tf32r(pa1.y), tf32r(pa1.z), tf32r(pa1.w));
        *(float4*)&As[0][br][bc]     = c0;
        *(float4*)&As[0][br][bc + 4] = c1;
    } else {
        As[0][ac + 0][ar] = tf32r(pa0.x); As[0][ac + 1][ar] = tf32r(pa0.y);
        As[0][ac + 2][ar] = tf32r(pa0.z); As[0][ac + 3][ar] = tf32r(pa0.w);
        As[0][ac + 4][ar] = tf32r(pa1.x); As[0][ac + 5][ar] = tf32r(pa1.y);
        As[0][ac + 6][ar] = tf32r(pa1.z); As[0][ac + 7][ar] = tf32r(pa1.w);
    }
    *(float4*)&Bs[0][br][bc]     = pb0;
    *(float4*)&Bs[0][br][bc + 4] = pb1;
    __syncthreads();

    for (int kt = 0; kt < NKT; kt++) {
        int cur = kt & 1;
        if (kt + 1 < NKT) {
            const float* An = ATRANS ? (Aptr + (size_t)(kt + 1) * GBK * HWSZ)
                                     : (Aptr + (kt + 1) * GBK);
            const float* Bn = Bptr + (size_t)(kt + 1) * GBK * NCAT;
            pa0 = *(const float4*)(An + 0);
            pa1 = *(const float4*)(An + 4);
            pb0 = *(const float4*)(Bn + 0);
            pb1 = *(const float4*)(Bn + 4);
        }
        #pragma unroll
        for (int ks = 0; ks < 2; ks++) {
            int kk = ks * 8;
            uint32_t af[2][4], bf[8][2];
            #pragma unroll
            for (int mt = 0; mt < 2; mt++) {
                int mb = wm * 32 + mt * 16;
                af[mt][0] = __float_as_uint(As[cur][kk + tid4    ][mb + gid    ]);
                af[mt][1] = __float_as_uint(As[cur][kk + tid4    ][mb + gid + 8]);
                af[mt][2] = __float_as_uint(As[cur][kk + tid4 + 4][mb + gid    ]);
                af[mt][3] = __float_as_uint(As[cur][kk + tid4 + 4][mb + gid + 8]);
            }
            #pragma unroll
            for (int nt = 0; nt < 8; nt++) {
                int nb = wn * 64 + nt * 8;
                bf[nt][0] = __float_as_uint(Bs[cur][kk + tid4    ][nb + gid]);
                bf[nt][1] = __float_as_uint(Bs[cur][kk + tid4 + 4][nb + gid]);
            }
            #pragma unroll
            for (int mt = 0; mt < 2; mt++)
                #pragma unroll
                for (int nt = 0; nt < 8; nt++)
                    mma_tf32(acc[mt][nt], af[mt], bf[nt]);
        }
        if (kt + 1 < NKT) {
            int nxt = cur ^ 1;
            if (ATRANS) {
                float4 c0 = make_float4(tf32r(pa0.x), tf32r(pa0.y), tf32r(pa0.z), tf32r(pa0.w));
                float4 c1 = make_float4(tf32r(pa1.x), tf32r(pa1.y), tf32r(pa1.z), tf32r(pa1.w));
                *(float4*)&As[nxt][br][bc]     = c0;
                *(float4*)&As[nxt][br][bc + 4] = c1;
            } else {
                As[nxt][ac + 0][ar] = tf32r(pa0.x); As[nxt][ac + 1][ar] = tf32r(pa0.y);
                As[nxt][ac + 2][ar] = tf32r(pa0.z); As[nxt][ac + 3][ar] = tf32r(pa0.w);
                As[nxt][ac + 4][ar] = tf32r(pa1.x); As[nxt][ac + 5][ar] = tf32r(pa1.y);
                As[nxt][ac + 6][ar] = tf32r(pa1.z); As[nxt][ac + 7][ar] = tf32r(pa1.w);
            }
            *(float4*)&Bs[nxt][br][bc]     = pb0;
            *(float4*)&Bs[nxt][br][bc + 4] = pb1;
            __syncthreads();
        }
    }

    // epilogue
    #pragma unroll
    for (int mt = 0; mt < 2; mt++) {
        int r0 = m0 + wm * 32 + mt * 16 + gid;
        #pragma unroll
        for (int nt = 0; nt < 8; nt++) {
            int cb = n0 + wn * 64 + nt * 8 + 2 * tid4;
            float b0 = bias[cb], b1 = bias[cb + 1];
            if (STORE_NCHW) {
                int n0b = r0 >> 12, hw0 = r0 & 4095;
                int n1b = (r0 + 8) >> 12, hw1 = (r0 + 8) & 4095;
                Cout[((size_t)n0b * CC + cb    ) * HWSZ + hw0] = acc[mt][nt][0] + b0;
                Cout[((size_t)n0b * CC + cb + 1) * HWSZ + hw0] = acc[mt][nt][1] + b1;
                Cout[((size_t)n1b * CC + cb    ) * HWSZ + hw1] = acc[mt][nt][2] + b0;
                Cout[((size_t)n1b * CC + cb + 1) * HWSZ + hw1] = acc[mt][nt][3] + b1;
            } else {
                Cout[(size_t)r0 * NCAT + cb]           = acc[mt][nt][0] + b0;
                Cout[(size_t)r0 * NCAT + cb + 1]       = acc[mt][nt][1] + b1;
                Cout[(size_t)(r0 + 8) * NCAT + cb]     = acc[mt][nt][2] + b0;
                Cout[(size_t)(r0 + 8) * NCAT + cb + 1] = acc[mt][nt][3] + b1;
            }
        }
    }
}

// ---------------------------------------------------------------------------
// 5+6) DCNv3 bilinear sampling with fused per-(t,g) softmax over P.
//      One warp = one (token, group), lane = channel.
// ---------------------------------------------------------------------------
__global__ void dcn_kernel() {
    int t = blockIdx.x;
    int g = threadIdx.x >> 5;
    int lane = threadIdx.x & 31;
    int n = t >> 12, hw = t & 4095, h = hw >> 6, w = hw & 63;

    const float* off = g_om + (size_t)t * NCAT + g * (PP * 2);
    const float* lg  = g_om + (size_t)t * NCAT + NOFF + g * PP;
    const float* xvb = g_xv + (size_t)n * HWSZ * CC + g * CG + lane;

    float e[PP];
    float mx = lg[0];
    #pragma unroll
    for (int p = 1; p < PP; p++) mx = fmaxf(mx, lg[p]);
    float s = 0.f;
    #pragma unroll
    for (int p = 0; p < PP; p++) { e[p] = __expf(lg[p] - mx); s += e[p]; }
    float inv = 1.0f / s;

    float acc = 0.f;
    #pragma unroll
    for (int p = 0; p < PP; p++) {
        float kx = (float)(p / 3 - 1);
        float ky = (float)(p % 3 - 1);
        float px = (float)w + 1.0f + 2.0f * (kx + off[p * 2 + 0]);
        float py = (float)h + 1.0f + 2.0f * (ky + off[p * 2 + 1]);
        float x0f = floorf(px), y0f = floorf(py);
        float wx = px - x0f, wy = py - y0f;
        int x0 = (int)x0f, y0 = (int)y0f;
        float m = e[p] * inv;

        float v00 = 0.f, v01 = 0.f, v10 = 0.f, v11 = 0.f;
        if (x0 >= 1 && x0 <= WW && y0 >= 1 && y0 <= HH)
            v00 = xvb[((size_t)(y0 - 1) * WW + (x0 - 1)) * CC];
        if (x0 + 1 >= 1 && x0 + 1 <= WW && y0 >= 1 && y0 <= HH)
            v01 = xvb[((size_t)(y0 - 1) * WW + x0) * CC];
        if (x0 >= 1 && x0 <= WW && y0 + 1 >= 1 && y0 + 1 <= HH)
            v10 = xvb[((size_t)y0 * WW + (x0 - 1)) * CC];
        if (x0 + 1 >= 1 && x0 + 1 <= WW && y0 + 1 >= 1 && y0 + 1 <= HH)
            v11 = xvb[((size_t)y0 * WW + x0) * CC];

        float top = v00 * (1.f - wx) + v01 * wx;
        float bot = v10 * (1.f - wx) + v11 * wx;
        acc = fmaf(m, top * (1.f - wy) + bot * wy, acc);
    }
    g_y[(size_t)t * CC + g * CG + lane] = acc;
}

// ---------------------------------------------------------------------------
extern "C" void kernel_launch(void* const* d_in, const int* in_sizes, int n_in,
                              void* d_out, int out_size) {
    const float* inputs = (const float*)d_in[0];
    const float* w_in   = (const float*)d_in[1];
    const float* b_in   = (const float*)d_in[2];
    const float* dw_k   = (const float*)d_in[3];
    const float* dw_b   = (const float*)d_in[4];
    const float* ln_g   = (const float*)d_in[5];
    const float* ln_b   = (const float*)d_in[6];
    const float* w_off  = (const float*)d_in[7];
    const float* b_off  = (const float*)d_in[8];
    const float* w_mask = (const float*)d_in[9];
    const float* b_mask = (const float*)d_in[10];
    const float* w_out  = (const float*)d_in[11];
    const float* b_out  = (const float*)d_in[12];
    float* out = (float*)d_out;

    static float *p_xv = nullptr, *p_x1 = nullptr, *p_om = nullptr, *p_y = nullptr,
                 *p_win = nullptr, *p_wout = nullptr, *p_wcat = nullptr, *p_bcat = nullptr;
    if (!p_xv) {
        cudaGetSymbolAddress((void**)&p_xv,   g_xv);
        cudaGetSymbolAddress((void**)&p_x1,   g_x1);
        cudaGetSymbolAddress((void**)&p_om,   g_om);
        cudaGetSymbolAddress((void**)&p_y,    g_y);
        cudaGetSymbolAddress((void**)&p_win,  g_win);
        cudaGetSymbolAddress((void**)&p_wout, g_wout);
        cudaGetSymbolAddress((void**)&p_wcat, g_wcat);
        cudaGetSymbolAddress((void**)&p_bcat, g_bcat);
    }

    // 0) pack + tf32-round weights
    pack_kernel<<<CC, CC>>>(w_in, w_off, b_off, w_mask, b_mask, w_out);
    // 1) depthwise conv (NCHW, raw input)
    conv_dw_kernel<<<NB * CC, 256>>>(inputs, dw_k, dw_b);
    // 2) value projection (tf32 MMA, A read directly from NCHW input)
    gemm_tf32<1, 0><<<dim3(2, MTOK / GBM), 256>>>(inputs, p_win, b_in, p_xv);
    // 3) LayerNorm + GELU + transpose to NHWC
    ln_gelu_kernel<<<MTOK / 32, 256>>>(ln_g, ln_b);
    // 4) offset + mask logits, fused (tf32 MMA)
    gemm_tf32<0, 0><<<dim3(2, MTOK / GBM), 256>>>(p_x1, p_wcat, p_bcat, p_om);
    // 5+6) softmax + deformable sampling
    dcn_kernel<<<MTOK, 256>>>();
    // 7) output projection, NCHW store (tf32 MMA)
    gemm_tf32<0, 1><<<dim3(2, MTOK / GBM), 256>>>(p_y, p_wout, b_out, out);
}

// round 4
// speedup vs baseline: 2.4928x; 1.2553x over previous
#include <cuda_runtime.h>
#include <math.h>
#include <stdint.h>

// Problem constants
#define NB   4
#define CC   256
#define HH   64
#define WW   64
#define HWSZ 4096        // H*W
#define MTOK 16384       // N*H*W tokens
#define GG   8
#define PP   9
#define CG   32          // C/G
#define NOFF 144         // G*P*2
#define NMSK 72          // G*P
#define NCAT 256         // padded off|mask column count

// Scratch (no allocs allowed)
__device__ float g_c1 [MTOK * CC];    // depthwise conv output, NCHW
__device__ float g_xv [MTOK * CC];    // value proj, NHWC
__device__ float g_x1 [MTOK * CC];    // conv+LN+GELU, NHWC
__device__ float g_om [MTOK * NCAT];  // offset(0..143) | mask logits(144..215) | pad
__device__ float g_y  [MTOK * CC];    // sampled output, NHWC

__device__ __forceinline__ float tf32r(float x) {
    uint32_t u;
    asm("cvt.rna.tf32.f32 %0, %1;" : "=r"(u) : "f"(x));
    return __uint_as_float(u);
}

__device__ __forceinline__ void mma_tf32(float d[4], const uint32_t a[4], const uint32_t b[2]) {
    asm("mma.sync.aligned.m16n8k8.row.col.f32.tf32.tf32.f32 "
        "{%0,%1,%2,%3}, {%4,%5,%6,%7}, {%8,%9}, {%0,%1,%2,%3};"
        : "+f"(d[0]), "+f"(d[1]), "+f"(d[2]), "+f"(d[3])
        : "r"(a[0]), "r"(a[1]), "r"(a[2]), "r"(a[3]), "r"(b[0]), "r"(b[1]));
}

// concat weight gather: [w_off | w_mask | 0]
__device__ __forceinline__ float catw(const float* __restrict__ w_off,
                                      const float* __restrict__ w_mask,
                                      int k, int col) {
    if (col < NOFF) return w_off[k * NOFF + col];
    if (col < NOFF + NMSK) return w_mask[k * NMSK + (col - NOFF)];
    return 0.f;
}

// ---------------------------------------------------------------------------
// TF32 GEMM body: C[M,256] = A[M,256] @ B[256,256] + bias
// CTA 128x128x16, 8 warps (4m x 2n), warp tile 32x64, double-buffered smem.
// ATRANS=1: A read from NCHW ([n][K][hw] per-n column-major).
// BKIND=0: plain B (tf32-rounded at staging). BKIND=2: concat [w_off|w_mask|0].
// STORE_NCHW=1: store to NCHW [4][256][4096].
// ---------------------------------------------------------------------------
#define GBM 128
#define GBN 128
#define GBK 16
#define SPAD 136
#define KTOT 256
#define NKT (KTOT / GBK)
#define SMEM_FLOATS (2 * GBK * SPAD * 2)   // 8704 floats = 34816 B

template<int ATRANS, int BKIND, int STORE_NCHW>
__device__ __forceinline__ void gemm_body(
    const float* __restrict__ A,
    const float* __restrict__ B0, const float* __restrict__ B1,
    const float* __restrict__ bias0, const float* __restrict__ bias1,
    float* __restrict__ Cout, int bx, int by, float* smem)
{
    float (*As)[GBK][SPAD] = (float (*)[GBK][SPAD])smem;
    float (*Bs)[GBK][SPAD] = (float (*)[GBK][SPAD])(smem + 2 * GBK * SPAD);

    int tid  = threadIdx.x;
    int lane = tid & 31;
    int warp = tid >> 5;
    int gid  = lane >> 2;
    int tid4 = lane & 3;
    int wm   = warp >> 1;
    int wn   = warp & 1;
    int m0   = by * GBM;
    int n0   = bx * GBN;

    int ar = tid >> 1;             // !ATRANS: A row (0..127)
    int ac = (tid & 1) * 8;        // !ATRANS: A k offset
    int br = tid >> 4;             // k row (0..15)
    int bc = (tid & 15) * 8;       // col offset

    const float* Aptr;
    if (ATRANS) {
        Aptr = A + (size_t)(m0 >> 12) * CC * HWSZ + (size_t)br * HWSZ + (m0 & 4095) + bc;
    } else {
        Aptr = A + (size_t)(m0 + ar) * KTOT + ac;
    }

    float acc[2][8][4];
    #pragma unroll
    for (int i = 0; i < 2; i++)
        #pragma unroll
        for (int j = 0; j < 8; j++)
            #pragma unroll
            for (int q = 0; q < 4; q++) acc[i][j][q] = 0.f;

    float4 pa0, pa1;
    float pv[8];

    // prologue: k-tile 0
    pa0 = *(const float4*)(Aptr + 0);
    pa1 = *(const float4*)(Aptr + 4);
    if (BKIND == 2) {
        #pragma unroll
        for (int j = 0; j < 8; j++) pv[j] = catw(B0, B1, br, n0 + bc + j);
    } else {
        float4 b0 = *(const float4*)(B0 + (size_t)br * CC + n0 + bc);
        float4 b1 = *(const float4*)(B0 + (size_t)br * CC + n0 + bc + 4);
        pv[0] = b0.x; pv[1] = b0.y; pv[2] = b0.z; pv[3] = b0.w;
        pv[4] = b1.x; pv[5] = b1.y; pv[6] = b1.z; pv[7] = b1.w;
    }
    if (ATRANS) {
        float4 c0 = make_float4(tf32r(pa0.x), tf32r(pa0.y), tf32r(pa0.z), tf32r(pa0.w));
        float4 c1 = make_float4(tf32r(pa1.x), tf32r(pa1.y), tf32r(pa1.z), tf32r(pa1.w));
        *(float4*)&As[0][br][bc]     = c0;
        *(float4*)&As[0][br][bc + 4] = c1;
    } else {
        As[0][ac + 0][ar] = tf32r(pa0.x); As[0][ac + 1][ar] = tf32r(pa0.y);
        As[0][ac + 2][ar] = tf32r(pa0.z); As[0][ac + 3][ar] = tf32r(pa0.w);
        As[0][ac + 4][ar] = tf32r(pa1.x); As[0][ac + 5][ar] = tf32r(pa1.y);
        As[0][ac + 6][ar] = tf32r(pa1.z); As[0][ac + 7][ar] = tf32r(pa1.w);
    }
    {
        float4 c0 = make_float4(tf32r(pv[0]), tf32r(pv[1]), tf32r(pv[2]), tf32r(pv[3]));
        float4 c1 = make_float4(tf32r(pv[4]), tf32r(pv[5]), tf32r(pv[6]), tf32r(pv[7]));
        *(float4*)&Bs[0][br][bc]     = c0;
        *(float4*)&Bs[0][br][bc + 4] = c1;
    }
    __syncthreads();

    for (int kt = 0; kt < NKT; kt++) {
        int cur = kt & 1;
        if (kt + 1 < NKT) {
            const float* An = ATRANS ? (Aptr + (size_t)(kt + 1) * GBK * HWSZ)
                                     : (Aptr + (kt + 1) * GBK);
            pa0 = *(const float4*)(An + 0);
            pa1 = *(const float4*)(An + 4);
            int kn = (kt + 1) * GBK + br;
            if (BKIND == 2) {
                #pragma unroll
                for (int j = 0; j < 8; j++) pv[j] = catw(B0, B1, kn, n0 + bc + j);
            } else {
                float4 b0 = *(const float4*)(B0 + (size_t)kn * CC + n0 + bc);
                float4 b1 = *(const float4*)(B0 + (size_t)kn * CC + n0 + bc + 4);
                pv[0] = b0.x; pv[1] = b0.y; pv[2] = b0.z; pv[3] = b0.w;
                pv[4] = b1.x; pv[5] = b1.y; pv[6] = b1.z; pv[7] = b1.w;
            }
        }
        #pragma unroll
        for (int ks = 0; ks < 2; ks++) {
            int kk = ks * 8;
            uint32_t af[2][4], bf[8][2];
            #pragma unroll
            for (int mt = 0; mt < 2; mt++) {
                int mb = wm * 32 + mt * 16;
                af[mt][0] = __float_as_uint(As[cur][kk + tid4    ][mb + gid    ]);
                af[mt][1] = __float_as_uint(As[cur][kk + tid4    ][mb + gid + 8]);
                af[mt][2] = __float_as_uint(As[cur][kk + tid4 + 4][mb + gid    ]);
                af[mt][3] = __float_as_uint(As[cur][kk + tid4 + 4][mb + gid + 8]);
            }
            #pragma unroll
            for (int nt = 0; nt < 8; nt++) {
                int nb = wn * 64 + nt * 8;
                bf[nt][0] = __float_as_uint(Bs[cur][kk + tid4    ][nb + gid]);
                bf[nt][1] = __float_as_uint(Bs[cur][kk + tid4 + 4][nb + gid]);
            }
            #pragma unroll
            for (int mt = 0; mt < 2; mt++)
                #pragma unroll
                for (int nt = 0; nt < 8; nt++)
                    mma_tf32(acc[mt][nt], af[mt], bf[nt]);
        }
        if (kt + 1 < NKT) {
            int nxt = cur ^ 1;
            if (ATRANS) {
                float4 c0 = make_float4(tf32r(pa0.x), tf32r(pa0.y), tf32r(pa0.z), tf32r(pa0.w));
                float4 c1 = make_float4(tf32r(pa1.x), tf32r(pa1.y), tf32r(pa1.z), tf32r(pa1.w));
                *(float4*)&As[nxt][br][bc]     = c0;
                *(float4*)&As[nxt][br][bc + 4] = c1;
            } else {
                As[nxt][ac + 0][ar] = tf32r(pa0.x); As[nxt][ac + 1][ar] = tf32r(pa0.y);
                As[nxt][ac + 2][ar] = tf32r(pa0.z); As[nxt][ac + 3][ar] = tf32r(pa0.w);
                As[nxt][ac + 4][ar] = tf32r(pa1.x); As[nxt][ac + 5][ar] = tf32r(pa1.y);
                As[nxt][ac + 6][ar] = tf32r(pa1.z); As[nxt][ac + 7][ar] = tf32r(pa1.w);
            }
            float4 c0 = make_float4(tf32r(pv[0]), tf32r(pv[1]), tf32r(pv[2]), tf32r(pv[3]));
            float4 c1 = make_float4(tf32r(pv[4]), tf32r(pv[5]), tf32r(pv[6]), tf32r(pv[7]));
            *(float4*)&Bs[nxt][br][bc]     = c0;
            *(float4*)&Bs[nxt][br][bc + 4] = c1;
            __syncthreads();
        }
    }

    // epilogue
    #pragma unroll
    for (int mt = 0; mt < 2; mt++) {
        int r0 = m0 + wm * 32 + mt * 16 + gid;
        #pragma unroll
        for (int nt = 0; nt < 8; nt++) {
            int cb = n0 + wn * 64 + nt * 8 + 2 * tid4;
            float b0, b1;
            if (BKIND == 2) {
                b0 = (cb < NOFF) ? bias0[cb] : (cb < NOFF + NMSK) ? bias1[cb - NOFF] : 0.f;
                int c1i = cb + 1;
                b1 = (c1i < NOFF) ? bias0[c1i] : (c1i < NOFF + NMSK) ? bias1[c1i - NOFF] : 0.f;
            } else {
                b0 = bias0[cb]; b1 = bias0[cb + 1];
            }
            if (STORE_NCHW) {
                int n0b = r0 >> 12, hw0 = r0 & 4095;
                int n1b = (r0 + 8) >> 12, hw1 = (r0 + 8) & 4095;
                Cout[((size_t)n0b * CC + cb    ) * HWSZ + hw0] = acc[mt][nt][0] + b0;
                Cout[((size_t)n0b * CC + cb + 1) * HWSZ + hw0] = acc[mt][nt][1] + b1;
                Cout[((size_t)n1b * CC + cb    ) * HWSZ + hw1] = acc[mt][nt][2] + b0;
                Cout[((size_t)n1b * CC + cb + 1) * HWSZ + hw1] = acc[mt][nt][3] + b1;
            } else {
                Cout[(size_t)r0 * NCAT + cb]           = acc[mt][nt][0] + b0;
                Cout[(size_t)r0 * NCAT + cb + 1]       = acc[mt][nt][1] + b1;
                Cout[(size_t)(r0 + 8) * NCAT + cb]     = acc[mt][nt][2] + b0;
                Cout[(size_t)(r0 + 8) * NCAT + cb + 1] = acc[mt][nt][3] + b1;
            }
        }
    }
}

// ---------------------------------------------------------------------------
// 1) Fused launch: blocks 0..255 do the value-proj GEMM (A straight from NCHW
//    input); blocks 256..1279 do the depthwise 3x3 conv (one (n,c) plane each).
//    Independent work, concurrent in one launch.
// ---------------------------------------------------------------------------
__global__ void __launch_bounds__(256, 2)
conv_gemm_kernel(const float* __restrict__ in,
                 const float* __restrict__ w_in,
                 const float* __restrict__ b_in,
                 const float* __restrict__ dwk,
                 const float* __restrict__ dwb) {
    __shared__ float smem[SMEM_FLOATS];
    if (blockIdx.x < 256) {
        gemm_body<1, 0, 0>(in, w_in, w_in, b_in, b_in, g_xv,
                           blockIdx.x & 1, blockIdx.x >> 1, smem);
        return;
    }
    // depthwise conv
    float (*sp)[66] = (float (*)[66])smem;
    int b = blockIdx.x - 256;
    int n = b >> 8, c = b & 255;
    int tid = threadIdx.x;

    for (int i = tid; i < 66 * 66; i += 256) ((float*)sp)[i] = 0.f;
    __syncthreads();

    const float* src = in + ((size_t)n * CC + c) * HWSZ;
    for (int i = tid; i < HWSZ; i += 256) {
        int h = i >> 6, w = i & 63;
        sp[h + 1][w + 1] = src[i];
    }
    __syncthreads();

    float k00 = dwk[0 * CC + c], k01 = dwk[1 * CC + c], k02 = dwk[2 * CC + c];
    float k10 = dwk[3 * CC + c], k11 = dwk[4 * CC + c], k12 = dwk[5 * CC + c];
    float k20 = dwk[6 * CC + c], k21 = dwk[7 * CC + c], k22 = dwk[8 * CC + c];
    float bb  = dwb[c];

    float* dst = g_c1 + ((size_t)n * CC + c) * HWSZ;
    for (int i = tid; i < HWSZ; i += 256) {
        int h = i >> 6, w = i & 63;
        float acc = bb;
        acc = fmaf(sp[h    ][w    ], k00, acc);
        acc = fmaf(sp[h    ][w + 1], k01, acc);
        acc = fmaf(sp[h    ][w + 2], k02, acc);
        acc = fmaf(sp[h + 1][w    ], k10, acc);
        acc = fmaf(sp[h + 1][w + 1], k11, acc);
        acc = fmaf(sp[h + 1][w + 2], k12, acc);
        acc = fmaf(sp[h + 2][w    ], k20, acc);
        acc = fmaf(sp[h + 2][w + 1], k21, acc);
        acc = fmaf(sp[h + 2][w + 2], k22, acc);
        dst[i] = acc;
    }
}

// plain GEMM wrappers
__global__ void __launch_bounds__(256, 2)
gemm_om_kernel(const float* __restrict__ A, const float* __restrict__ w_off,
               const float* __restrict__ w_mask, const float* __restrict__ b_off,
               const float* __restrict__ b_mask, float* __restrict__ Cout) {
    __shared__ float smem[SMEM_FLOATS];
    gemm_body<0, 2, 0>(A, w_off, w_mask, b_off, b_mask, Cout,
                       blockIdx.x & 1, blockIdx.x >> 1, smem);
}

__global__ void __launch_bounds__(256, 2)
gemm_out_kernel(const float* __restrict__ A, const float* __restrict__ B,
                const float* __restrict__ bias, float* __restrict__ Cout) {
    __shared__ float smem[SMEM_FLOATS];
    gemm_body<0, 0, 1>(A, B, B, bias, bias, Cout,
                       blockIdx.x & 1, blockIdx.x >> 1, smem);
}

// ---------------------------------------------------------------------------
// 2) LayerNorm + exact GELU with NCHW -> NHWC transpose.
// ---------------------------------------------------------------------------
__global__ void __launch_bounds__(256)
ln_gelu_kernel(const float* __restrict__ lng, const float* __restrict__ lnb) {
    __shared__ float tile[256][33];
    __shared__ float smu[32], srs[32];

    int tid = threadIdx.x;
    int t0 = blockIdx.x * 32;
    int n = t0 >> 12, hw0 = t0 & 4095;

    const float* src = g_c1 + (size_t)n * CC * HWSZ + hw0;
    int tx = tid & 31, ty = tid >> 5;
    #pragma unroll 4
    for (int cc = 0; cc < 32; cc++) {
        int ch = cc * 8 + ty;
        tile[ch][tx] = src[(size_t)ch * HWSZ + tx];
    }
    __syncthreads();

    int tok = tid >> 3, thr = tid & 7;
    float s1 = 0.f, s2 = 0.f;
    #pragma unroll 8
    for (int i = 0; i < 32; i++) {
        float v = tile[thr + 8 * i][tok];
        s1 += v; s2 += v * v;
    }
    #pragma unroll
    for (int d = 1; d < 8; d <<= 1) {
        s1 += __shfl_xor_sync(0xffffffffu, s1, d);
        s2 += __shfl_xor_sync(0xffffffffu, s2, d);
    }
    if (thr == 0) {
        float mu = s1 * (1.0f / 256.0f);
        float var = s2 * (1.0f / 256.0f) - mu * mu;
        smu[tok] = mu;
        srs[tok] = rsqrtf(var + 1e-6f);
    }
    __syncthreads();

    float gma = lng[tid], bta = lnb[tid];
    #pragma unroll 4
    for (int j = 0; j < 32; j++) {
        float v = (tile[tid][j] - smu[j]) * srs[j] * gma + bta;
        v = 0.5f * v * (1.0f + erff(v * 0.70710678118654752f));
        g_x1[(size_t)(t0 + j) * CC + tid] = v;
    }
}

// ---------------------------------------------------------------------------
// 5+6) DCNv3 sampling, fused softmax. 8 lanes x float4 per group;
//      block = 4 adjacent tokens x 64 threads (8 groups x 8 lanes).
// ---------------------------------------------------------------------------
__global__ void __launch_bounds__(256)
dcn_kernel() {
    int tid = threadIdx.x;
    int t   = blockIdx.x * 4 + (tid >> 6);
    int sub = tid & 63;
    int g   = sub >> 3, l8 = sub & 7;
    int n = t >> 12, hw = t & 4095, h = hw >> 6, w = hw & 63;

    const float* off = g_om + (size_t)t * NCAT + g * (PP * 2);
    const float* lg  = g_om + (size_t)t * NCAT + NOFF + g * PP;
    const float4* xvb = (const float4*)(g_xv + (size_t)n * HWSZ * CC + g * CG) + l8;
    // pixel stride in float4 units: CC/4 = 64

    float e[PP];
    float mx = lg[0];
    #pragma unroll
    for (int p = 1; p < PP; p++) mx = fmaxf(mx, lg[p]);
    float s = 0.f;
    #pragma unroll
    for (int p = 0; p < PP; p++) { e[p] = __expf(lg[p] - mx); s += e[p]; }
    float inv = 1.0f / s;

    float ax = 0.f, ay = 0.f, az = 0.f, aw = 0.f;
    #pragma unroll
    for (int p = 0; p < PP; p++) {
        float kx = (float)(p / 3 - 1);
        float ky = (float)(p % 3 - 1);
        float px = (float)w + 1.0f + 2.0f * (kx + off[p * 2 + 0]);
        float py = (float)h + 1.0f + 2.0f * (ky + off[p * 2 + 1]);
        float x0f = floorf(px), y0f = floorf(py);
        float wx = px - x0f, wy = py - y0f;
        int x0 = (int)x0f, y0 = (int)y0f;
        float m = e[p] * inv;

        bool bx0 = (x0 >= 1) & (x0 <= WW);
        bool bx1 = (x0 >= 0) & (x0 <= WW - 1);
        bool by0 = (y0 >= 1) & (y0 <= HH);
        bool by1 = (y0 >= 0) & (y0 <= HH - 1);

        float4 v00 = {0,0,0,0}, v01 = {0,0,0,0}, v10 = {0,0,0,0}, v11 = {0,0,0,0};
        if (bx0 & by0) v00 = xvb[(size_t)((y0 - 1) * WW + (x0 - 1)) * (CC / 4)];
        if (bx1 & by0) v01 = xvb[(size_t)((y0 - 1) * WW + x0) * (CC / 4)];
        if (bx0 & by1) v10 = xvb[(size_t)(y0 * WW + (x0 - 1)) * (CC / 4)];
        if (bx1 & by1) v11 = xvb[(size_t)(y0 * WW + x0) * (CC / 4)];

        float w00 = m * (1.f - wx) * (1.f - wy);
        float w01 = m * wx * (1.f - wy);
        float w10 = m * (1.f - wx) * wy;
        float w11 = m * wx * wy;

        ax = fmaf(w00, v00.x, fmaf(w01, v01.x, fmaf(w10, v10.x, fmaf(w11, v11.x, ax))));
        ay = fmaf(w00, v00.y, fmaf(w01, v01.y, fmaf(w10, v10.y, fmaf(w11, v11.y, ay))));
        az = fmaf(w00, v00.z, fmaf(w01, v01.z, fmaf(w10, v10.z, fmaf(w11, v11.z, az))));
        aw = fmaf(w00, v00.w, fmaf(w01, v01.w, fmaf(w10, v10.w, fmaf(w11, v11.w, aw))));
    }
    ((float4*)(g_y + (size_t)t * CC + g * CG))[l8] = make_float4(ax, ay, az, aw);
}

// ---------------------------------------------------------------------------
extern "C" void kernel_launch(void* const* d_in, const int* in_sizes, int n_in,
                              void* d_out, int out_size) {
    const float* inputs = (const float*)d_in[0];
    const float* w_in   = (const float*)d_in[1];
    const float* b_in   = (const float*)d_in[2];
    const float* dw_k   = (const float*)d_in[3];
    const float* dw_b   = (const float*)d_in[4];
    const float* ln_g   = (const float*)d_in[5];
    const float* ln_b   = (const float*)d_in[6];
    const float* w_off  = (const float*)d_in[7];
    const float* b_off  = (const float*)d_in[8];
    const float* w_mask = (const float*)d_in[9];
    const float* b_mask = (const float*)d_in[10];
    const float* w_out  = (const float*)d_in[11];
    const float* b_out  = (const float*)d_in[12];
    float* out = (float*)d_out;

    static float *p_x1 = nullptr, *p_om = nullptr, *p_y = nullptr;
    if (!p_x1) {
        cudaGetSymbolAddress((void**)&p_x1, g_x1);
        cudaGetSymbolAddress((void**)&p_om, g_om);
        cudaGetSymbolAddress((void**)&p_y,  g_y);
    }

    // 1) fused: value-proj GEMM (256 blocks) + depthwise conv (1024 blocks)
    conv_gemm_kernel<<<256 + NB * CC, 256>>>(inputs, w_in, b_in, dw_k, dw_b);
    // 2) LayerNorm + GELU + transpose to NHWC
    ln_gelu_kernel<<<MTOK / 32, 256>>>(ln_g, ln_b);
    // 3) offset + mask logits (concat B staged in-kernel)
    gemm_om_kernel<<<256, 256>>>(p_x1, w_off, w_mask, b_off, b_mask, p_om);
    // 4) softmax + deformable sampling
    dcn_kernel<<<MTOK / 4, 256>>>();
    // 5) output projection, NCHW store
    gemm_out_kernel<<<256, 256>>>(p_y, w_out, b_out, out);
}